// round 1
// baseline (speedup 1.0000x reference)
#include <cuda_runtime.h>
#include <cuda_bf16.h>
#include <cstddef>

// Problem constants (fixed-shape problem)
#define BATCH 64
#define SEQ   2048
#define DIM   512
#define NFINE 16
#define MSPAN 512

// Scratch (device globals; no allocations allowed)
__device__ int g_nB[BATCH];
__device__ int g_Bpos[BATCH * (MSPAN + 1)];

// ---------------------------------------------------------------------------
// Kernel A: per batch row, find positions of B tags (compact list) via
// block-wide exclusive scan. 64 blocks x 256 threads, 8 tokens/thread.
// ---------------------------------------------------------------------------
__global__ void __launch_bounds__(256) span_index_kernel(
    const int* __restrict__ labels, const int* __restrict__ pB)
{
    const int b = blockIdx.x;
    const int t = threadIdx.x;
    const int cB = *pB;
    const int* row = labels + (size_t)b * SEQ;

    const int s0 = t * 8;
    int flags[8];
    int cnt = 0;
#pragma unroll
    for (int j = 0; j < 8; j++) {
        int lab = row[s0 + j];
        flags[j] = (lab == cB) ? 1 : 0;
        cnt += flags[j];
    }

    // exclusive scan of per-thread counts over 256 threads
    const int lane = t & 31;
    const int warp = t >> 5;
    int inc = cnt;
#pragma unroll
    for (int o = 1; o < 32; o <<= 1) {
        int v = __shfl_up_sync(0xffffffffu, inc, o);
        if (lane >= o) inc += v;
    }
    __shared__ int wsum[8];
    if (lane == 31) wsum[warp] = inc;
    __syncthreads();
    if (t < 8) {
        int v = wsum[t];
#pragma unroll
        for (int o = 1; o < 8; o <<= 1) {
            int u = __shfl_up_sync(0xffu, v, o);
            if (t >= o) v += u;
        }
        wsum[t] = v;  // inclusive warp sums
    }
    __syncthreads();
    int excl = inc - cnt + (warp > 0 ? wsum[warp - 1] : 0);

    int idx = excl;
#pragma unroll
    for (int j = 0; j < 8; j++) {
        if (flags[j]) {
            if (idx <= MSPAN) g_Bpos[b * (MSPAN + 1) + idx] = s0 + j;
            idx++;
        }
    }
    if (t == 255) g_nB[b] = excl + cnt;  // total B count for the row
}

// ---------------------------------------------------------------------------
// Kernel B: warp-per-span. slot_embs transposed into shared [16][512].
// Each contributing token row: lane owns d = 4*lane + 128*j (j=0..3),
// conflict-free LDS.128 on W, perfectly coalesced LDG.128 on hidden.
// ---------------------------------------------------------------------------
__device__ __forceinline__ void accum_row(
    float acc[NFINE], const float* __restrict__ row,
    int lane, const float* __restrict__ Wsh)
{
    const float4* h4 = reinterpret_cast<const float4*>(row);
    const float4* W4 = reinterpret_cast<const float4*>(Wsh);
#pragma unroll
    for (int j = 0; j < 4; j++) {
        float4 h = __ldg(h4 + lane + 32 * j);
#pragma unroll
        for (int f = 0; f < NFINE; f++) {
            float4 wv = W4[f * (DIM / 4) + lane + 32 * j];
            acc[f] = fmaf(h.x, wv.x,
                     fmaf(h.y, wv.y,
                     fmaf(h.z, wv.z,
                     fmaf(h.w, wv.w, acc[f]))));
        }
    }
}

__global__ void __launch_bounds__(256) span_project_kernel(
    const float* __restrict__ hidden,
    const float* __restrict__ slot,   // [DIM][NFINE]
    const int*   __restrict__ labels,
    const int*   __restrict__ pI,
    float* __restrict__ out)          // [BATCH][MSPAN][NFINE]
{
    __shared__ float Wsh[NFINE * DIM];  // transposed: Wsh[f*512 + d]
    for (int i = threadIdx.x; i < DIM * NFINE; i += blockDim.x) {
        int d = i >> 4;
        int f = i & 15;
        Wsh[f * DIM + d] = slot[i];
    }
    __syncthreads();

    const int cI = *pI;
    const int lane = threadIdx.x & 31;
    const int wid  = threadIdx.x >> 5;
    const int gw = blockIdx.x * 8 + wid;
    const int nwarps = gridDim.x * 8;

    for (int w = gw; w < BATCH * MSPAN; w += nwarps) {
        const int b = w >> 9;      // / MSPAN
        const int k = w & (MSPAN - 1);
        const int nb = g_nB[b];
        if (k >= nb) continue;     // no such span; output stays zero

        const int* bp = g_Bpos + b * (MSPAN + 1);
        const int p = bp[k];
        const int pend = (k + 1 < nb) ? bp[k + 1] : SEQ;

        const float* hbase = hidden + (size_t)b * SEQ * DIM;
        float acc[NFINE];
#pragma unroll
        for (int f = 0; f < NFINE; f++) acc[f] = 0.0f;

        // B-tagged head token always contributes
        accum_row(acc, hbase + (size_t)p * DIM, lane, Wsh);

        // I-tagged tokens strictly inside (p, pend)
        const int* lrow = labels + (size_t)b * SEQ;
        for (int s = p + 1; s < pend; s += 32) {
            int ss = s + lane;
            bool hit = (ss < pend) && (lrow[ss] == cI);
            unsigned m = __ballot_sync(0xffffffffu, hit);
            while (m) {
                int j = __ffs(m) - 1;
                m &= m - 1;
                accum_row(acc, hbase + (size_t)(s + j) * DIM, lane, Wsh);
            }
        }

        // butterfly reduce each of the 16 accumulators across the warp
#pragma unroll
        for (int f = 0; f < NFINE; f++) {
            float v = acc[f];
            v += __shfl_xor_sync(0xffffffffu, v, 16);
            v += __shfl_xor_sync(0xffffffffu, v, 8);
            v += __shfl_xor_sync(0xffffffffu, v, 4);
            v += __shfl_xor_sync(0xffffffffu, v, 2);
            v += __shfl_xor_sync(0xffffffffu, v, 1);
            acc[f] = v;  // now identical on all lanes
        }
        // lane f writes output element f (no dynamic register indexing)
        float v = acc[0];
#pragma unroll
        for (int f = 1; f < NFINE; f++)
            if (lane == f) v = acc[f];
        if (lane < NFINE)
            out[(size_t)w * NFINE + lane] = v;
    }
}

// ---------------------------------------------------------------------------
// kernel_launch
// Inputs (metadata order): hidden [B,S,D] f32, slot_embs [D,16] f32,
// bin_labels [B,S] i32, coarse_B_index i32 scalar, coarse_I_index i32 scalar,
// max_spans i32 scalar. Output: [B, 512, 16] f32.
// ---------------------------------------------------------------------------
extern "C" void kernel_launch(void* const* d_in, const int* in_sizes, int n_in,
                              void* d_out, int out_size)
{
    const float* hidden = (const float*)d_in[0];
    const float* slot   = (const float*)d_in[1];
    const int*   labels = (const int*)d_in[2];
    const int*   pB     = (const int*)d_in[3];
    const int*   pI     = (const int*)d_in[4];
    float* out = (float*)d_out;

    // absent spans must be exact zeros; harness poisons d_out
    cudaMemsetAsync(out, 0, (size_t)out_size * sizeof(float), 0);

    span_index_kernel<<<BATCH, 256>>>(labels, pB);

    // persistent-ish grid: 7 blocks/SM (32KB smem each), 148 SMs
    span_project_kernel<<<148 * 7, 256>>>(hidden, slot, labels, pI, out);
}

// round 2
// speedup vs baseline: 1.8837x; 1.8837x over previous
#include <cuda_runtime.h>
#include <cuda_bf16.h>
#include <cstddef>

#define BATCH 64
#define SEQ   2048
#define DIM   512
#define NFINE 16
#define MSPAN 512

__device__ int g_nB[BATCH];
__device__ int g_Bpos[BATCH * (MSPAN + 1)];

// ---------------------------------------------------------------------------
// Kernel A: per batch row, compact B-tag positions via block-wide scan.
// ---------------------------------------------------------------------------
__global__ void __launch_bounds__(256) span_index_kernel(
    const int* __restrict__ labels, const int* __restrict__ pB)
{
    const int b = blockIdx.x;
    const int t = threadIdx.x;
    const int cB = *pB;
    const int* row = labels + (size_t)b * SEQ;

    const int s0 = t * 8;
    int flags[8];
    int cnt = 0;
#pragma unroll
    for (int j = 0; j < 8; j++) {
        int lab = row[s0 + j];
        flags[j] = (lab == cB) ? 1 : 0;
        cnt += flags[j];
    }

    const int lane = t & 31;
    const int warp = t >> 5;
    int inc = cnt;
#pragma unroll
    for (int o = 1; o < 32; o <<= 1) {
        int v = __shfl_up_sync(0xffffffffu, inc, o);
        if (lane >= o) inc += v;
    }
    __shared__ int wsum[8];
    if (lane == 31) wsum[warp] = inc;
    __syncthreads();
    if (t < 8) {
        int v = wsum[t];
#pragma unroll
        for (int o = 1; o < 8; o <<= 1) {
            int u = __shfl_up_sync(0xffu, v, o);
            if (t >= o) v += u;
        }
        wsum[t] = v;
    }
    __syncthreads();
    int excl = inc - cnt + (warp > 0 ? wsum[warp - 1] : 0);

    int idx = excl;
#pragma unroll
    for (int j = 0; j < 8; j++) {
        if (flags[j]) {
            if (idx <= MSPAN) g_Bpos[b * (MSPAN + 1) + idx] = s0 + j;
            idx++;
        }
    }
    if (t == 255) g_nB[b] = excl + cnt;
}

// ---------------------------------------------------------------------------
// Kernel B: warp-per-span, SUM-THEN-PROJECT.
// Row accumulation: lane owns dims {4*lane+128*j}, pure FADD on float4,
// 4 independent LDG.128 per lane per row (MLP=4).
// Projection: once per span, W (transposed) from shared, conflict-free LDS.128.
// ---------------------------------------------------------------------------
__global__ void __launch_bounds__(256, 3) span_project_kernel(
    const float* __restrict__ hidden,
    const float* __restrict__ slot,   // [DIM][NFINE]
    const int*   __restrict__ labels,
    const int*   __restrict__ pI,
    float* __restrict__ out)          // [BATCH][MSPAN][NFINE]
{
    __shared__ float Wsh[NFINE * DIM];  // transposed: Wsh[f*512 + d]
    for (int i = threadIdx.x; i < DIM * NFINE; i += blockDim.x) {
        int d = i >> 4;
        int f = i & 15;
        Wsh[f * DIM + d] = slot[i];
    }
    __syncthreads();

    const int cI = *pI;
    const int lane = threadIdx.x & 31;
    const int wid  = threadIdx.x >> 5;
    const int gw = blockIdx.x * 8 + wid;
    const int nwarps = gridDim.x * 8;
    const float4* W4 = reinterpret_cast<const float4*>(Wsh);

    for (int w = gw; w < BATCH * MSPAN; w += nwarps) {
        const int b = w >> 9;
        const int k = w & (MSPAN - 1);
        const int nb = g_nB[b];
        if (k >= nb) continue;

        const int* bp = g_Bpos + b * (MSPAN + 1);
        const int p = bp[k];
        const int pend = (k + 1 < nb) ? bp[k + 1] : SEQ;

        const float* hbase = hidden + (size_t)b * SEQ * DIM;

        // ---- segment sum into per-lane feature quad (16 dims/lane) ----
        float4 F0, F1, F2, F3;
        {
            const float4* h4 = reinterpret_cast<const float4*>(hbase + (size_t)p * DIM);
            F0 = __ldg(h4 + lane);
            F1 = __ldg(h4 + lane + 32);
            F2 = __ldg(h4 + lane + 64);
            F3 = __ldg(h4 + lane + 96);
        }
        const int* lrow = labels + (size_t)b * SEQ;
        for (int s = p + 1; s < pend; s += 32) {
            int ss = s + lane;
            bool hit = (ss < pend) && (lrow[ss] == cI);
            unsigned m = __ballot_sync(0xffffffffu, hit);
            while (m) {
                int j = __ffs(m) - 1;
                m &= m - 1;
                const float4* h4 =
                    reinterpret_cast<const float4*>(hbase + (size_t)(s + j) * DIM);
                float4 a = __ldg(h4 + lane);
                float4 c1 = __ldg(h4 + lane + 32);
                float4 c2 = __ldg(h4 + lane + 64);
                float4 c3 = __ldg(h4 + lane + 96);
                F0.x += a.x;  F0.y += a.y;  F0.z += a.z;  F0.w += a.w;
                F1.x += c1.x; F1.y += c1.y; F1.z += c1.z; F1.w += c1.w;
                F2.x += c2.x; F2.y += c2.y; F2.z += c2.z; F2.w += c2.w;
                F3.x += c3.x; F3.y += c3.y; F3.z += c3.z; F3.w += c3.w;
            }
        }

        // ---- project once per span: acc[f] = sum over this lane's 16 dims ----
        float acc[NFINE];
#pragma unroll
        for (int f = 0; f < NFINE; f++) acc[f] = 0.0f;
#pragma unroll
        for (int f = 0; f < NFINE; f++) {
            float4 w0 = W4[f * (DIM / 4) + lane];
            float4 w1 = W4[f * (DIM / 4) + lane + 32];
            float4 w2 = W4[f * (DIM / 4) + lane + 64];
            float4 w3 = W4[f * (DIM / 4) + lane + 96];
            float v = 0.0f;
            v = fmaf(F0.x, w0.x, v); v = fmaf(F0.y, w0.y, v);
            v = fmaf(F0.z, w0.z, v); v = fmaf(F0.w, w0.w, v);
            v = fmaf(F1.x, w1.x, v); v = fmaf(F1.y, w1.y, v);
            v = fmaf(F1.z, w1.z, v); v = fmaf(F1.w, w1.w, v);
            v = fmaf(F2.x, w2.x, v); v = fmaf(F2.y, w2.y, v);
            v = fmaf(F2.z, w2.z, v); v = fmaf(F2.w, w2.w, v);
            v = fmaf(F3.x, w3.x, v); v = fmaf(F3.y, w3.y, v);
            v = fmaf(F3.z, w3.z, v); v = fmaf(F3.w, w3.w, v);
            acc[f] = v;
        }

        // ---- butterfly reduce 16 accumulators across warp ----
#pragma unroll
        for (int f = 0; f < NFINE; f++) {
            float v = acc[f];
            v += __shfl_xor_sync(0xffffffffu, v, 16);
            v += __shfl_xor_sync(0xffffffffu, v, 8);
            v += __shfl_xor_sync(0xffffffffu, v, 4);
            v += __shfl_xor_sync(0xffffffffu, v, 2);
            v += __shfl_xor_sync(0xffffffffu, v, 1);
            acc[f] = v;
        }
        float v = acc[0];
#pragma unroll
        for (int f = 1; f < NFINE; f++)
            if (lane == f) v = acc[f];
        if (lane < NFINE)
            out[(size_t)w * NFINE + lane] = v;
    }
}

extern "C" void kernel_launch(void* const* d_in, const int* in_sizes, int n_in,
                              void* d_out, int out_size)
{
    const float* hidden = (const float*)d_in[0];
    const float* slot   = (const float*)d_in[1];
    const int*   labels = (const int*)d_in[2];
    const int*   pB     = (const int*)d_in[3];
    const int*   pI     = (const int*)d_in[4];
    float* out = (float*)d_out;

    cudaMemsetAsync(out, 0, (size_t)out_size * sizeof(float), 0);

    span_index_kernel<<<BATCH, 256>>>(labels, pB);

    // 3 blocks/SM target (launch_bounds), grid-stride covers remainder
    span_project_kernel<<<148 * 3, 256>>>(hidden, slot, labels, pI, out);
}

// round 3
// speedup vs baseline: 2.4760x; 1.3144x over previous
#include <cuda_runtime.h>
#include <cstddef>
#include <cstdint>

#define BATCH 64
#define SEQ   2048
#define DIM   512
#define NFINE 16
#define MSPAN 512

typedef unsigned long long u64;

// Blackwell packed fp32x2 math (SASS FFMA2 / FADD2) — PTX-only, ptxas won't auto-fuse.
#define FMA2(d,a,b,c) asm("fma.rn.f32x2 %0, %1, %2, %3;" : "=l"(d) : "l"(a), "l"(b), "l"(c))
#define ADD2(d,a,b)   asm("add.rn.f32x2 %0, %1, %2;" : "=l"(d) : "l"(a), "l"(b))

__device__ int g_nB[BATCH];
__device__ int g_Bpos[BATCH * (MSPAN + 1)];

// ---------------------------------------------------------------------------
// Kernel A: per batch row, compact B-tag positions via block-wide scan.
// ---------------------------------------------------------------------------
__global__ void __launch_bounds__(256) span_index_kernel(
    const int* __restrict__ labels, const int* __restrict__ pB)
{
    const int b = blockIdx.x;
    const int t = threadIdx.x;
    const int cB = *pB;
    const int* row = labels + (size_t)b * SEQ;

    const int s0 = t * 8;
    int flags[8];
    int cnt = 0;
#pragma unroll
    for (int j = 0; j < 8; j++) {
        int lab = row[s0 + j];
        flags[j] = (lab == cB) ? 1 : 0;
        cnt += flags[j];
    }

    const int lane = t & 31;
    const int warp = t >> 5;
    int inc = cnt;
#pragma unroll
    for (int o = 1; o < 32; o <<= 1) {
        int v = __shfl_up_sync(0xffffffffu, inc, o);
        if (lane >= o) inc += v;
    }
    __shared__ int wsum[8];
    if (lane == 31) wsum[warp] = inc;
    __syncthreads();
    if (t < 8) {
        int v = wsum[t];
#pragma unroll
        for (int o = 1; o < 8; o <<= 1) {
            int u = __shfl_up_sync(0xffu, v, o);
            if (t >= o) v += u;
        }
        wsum[t] = v;
    }
    __syncthreads();
    int excl = inc - cnt + (warp > 0 ? wsum[warp - 1] : 0);

    int idx = excl;
#pragma unroll
    for (int j = 0; j < 8; j++) {
        if (flags[j]) {
            if (idx <= MSPAN) g_Bpos[b * (MSPAN + 1) + idx] = s0 + j;
            idx++;
        }
    }
    if (t == 255) g_nB[b] = excl + cnt;
}

// ---------------------------------------------------------------------------
// Segment-sum one span's feature into 8 packed f32x2 regs per lane
// (lane owns dims {4*lane+128j .. +3}, j=0..3).
// ---------------------------------------------------------------------------
__device__ __forceinline__ void accum_span(
    u64 F[8], const float* __restrict__ hbase, const int* __restrict__ lrow,
    int p, int pend, int cI, int lane)
{
    {
        const ulonglong2* h2 =
            reinterpret_cast<const ulonglong2*>(hbase + (size_t)p * DIM);
        ulonglong2 a = __ldg(h2 + lane);
        ulonglong2 b = __ldg(h2 + lane + 32);
        ulonglong2 c = __ldg(h2 + lane + 64);
        ulonglong2 d = __ldg(h2 + lane + 96);
        F[0] = a.x; F[1] = a.y; F[2] = b.x; F[3] = b.y;
        F[4] = c.x; F[5] = c.y; F[6] = d.x; F[7] = d.y;
    }
    for (int s = p + 1; s < pend; s += 32) {
        int ss = s + lane;
        bool hit = (ss < pend) && (__ldg(lrow + ss) == cI);
        unsigned m = __ballot_sync(0xffffffffu, hit);
        while (m) {
            int j = __ffs(m) - 1;
            m &= m - 1;
            const ulonglong2* h2 =
                reinterpret_cast<const ulonglong2*>(hbase + (size_t)(s + j) * DIM);
            ulonglong2 a = __ldg(h2 + lane);
            ulonglong2 b = __ldg(h2 + lane + 32);
            ulonglong2 c = __ldg(h2 + lane + 64);
            ulonglong2 d = __ldg(h2 + lane + 96);
            ADD2(F[0], F[0], a.x); ADD2(F[1], F[1], a.y);
            ADD2(F[2], F[2], b.x); ADD2(F[3], F[3], b.y);
            ADD2(F[4], F[4], c.x); ADD2(F[5], F[5], c.y);
            ADD2(F[6], F[6], d.x); ADD2(F[7], F[7], d.y);
        }
    }
}

// ---------------------------------------------------------------------------
// Tree-fold 4 per-lane partials (filters 4g..4g+3) across the warp in 6 SHFLs,
// then 4 lanes write. floc = 2*bit4(lane) + bit3(lane).
// ---------------------------------------------------------------------------
__device__ __forceinline__ void fold_write(
    const float sc[4], bool valid, float* __restrict__ dst, int lane)
{
    float send0 = (lane & 16) ? sc[0] : sc[2];
    float r0 = __shfl_xor_sync(0xffffffffu, send0, 16);
    float n0 = ((lane & 16) ? sc[2] : sc[0]) + r0;
    float send1 = (lane & 16) ? sc[1] : sc[3];
    float r1 = __shfl_xor_sync(0xffffffffu, send1, 16);
    float n1 = ((lane & 16) ? sc[3] : sc[1]) + r1;

    float send = (lane & 8) ? n0 : n1;
    float r = __shfl_xor_sync(0xffffffffu, send, 8);
    float v = ((lane & 8) ? n1 : n0) + r;

    v += __shfl_xor_sync(0xffffffffu, v, 4);
    v += __shfl_xor_sync(0xffffffffu, v, 2);
    v += __shfl_xor_sync(0xffffffffu, v, 1);

    if (valid && (lane & 7) == 0) {
        int floc = (((lane >> 4) & 1) << 1) | ((lane >> 3) & 1);
        dst[floc] = v;
    }
}

// ---------------------------------------------------------------------------
// Kernel B: warp handles TWO spans; sum-then-project; W LDS shared by both
// spans; packed f32x2 FMA; grouped 6-shfl folds.
// ---------------------------------------------------------------------------
__global__ void __launch_bounds__(256, 3) span_project_kernel(
    const float* __restrict__ hidden,
    const float* __restrict__ slot,   // [DIM][NFINE]
    const int*   __restrict__ labels,
    const int*   __restrict__ pI,
    float* __restrict__ out)          // [BATCH][MSPAN][NFINE]
{
    __shared__ __align__(16) float Wsh[NFINE * DIM];  // Wsh[f*512 + d]
    for (int i = threadIdx.x; i < DIM * NFINE; i += blockDim.x) {
        int d = i >> 4;
        int f = i & 15;
        Wsh[f * DIM + d] = slot[i];
    }
    __syncthreads();
    const ulonglong2* W2 = reinterpret_cast<const ulonglong2*>(Wsh);

    const int cI = *pI;
    const int lane = threadIdx.x & 31;
    const int wid  = threadIdx.x >> 5;
    const int gw = blockIdx.x * 8 + wid;
    const int nwarps = gridDim.x * 8;
    const int NPAIR = BATCH * MSPAN / 2;

    for (int wp = gw; wp < NPAIR; wp += nwarps) {
        const int w0 = wp * 2;
        const int w1 = w0 + 1;
        const int b0 = w0 >> 9, k0 = w0 & (MSPAN - 1);
        const int b1 = w1 >> 9, k1 = w1 & (MSPAN - 1);
        const int nb0 = g_nB[b0];
        const int nb1 = (b1 == b0) ? nb0 : g_nB[b1];
        const bool v0 = (k0 < nb0);
        const bool v1 = (k1 < nb1);
        if (!v0 && !v1) continue;

        u64 F0[8], F1[8];
#pragma unroll
        for (int i = 0; i < 8; i++) { F0[i] = 0ull; F1[i] = 0ull; }

        if (v0) {
            const int* bp = g_Bpos + b0 * (MSPAN + 1);
            int p = bp[k0];
            int pend = (k0 + 1 < nb0) ? bp[k0 + 1] : SEQ;
            accum_span(F0, hidden + (size_t)b0 * SEQ * DIM,
                       labels + (size_t)b0 * SEQ, p, pend, cI, lane);
        }
        if (v1) {
            const int* bp = g_Bpos + b1 * (MSPAN + 1);
            int p = bp[k1];
            int pend = (k1 + 1 < nb1) ? bp[k1 + 1] : SEQ;
            accum_span(F1, hidden + (size_t)b1 * SEQ * DIM,
                       labels + (size_t)b1 * SEQ, p, pend, cI, lane);
        }

        // projection: 4 groups of 4 filters; W loads shared by both spans
#pragma unroll
        for (int g = 0; g < 4; g++) {
            float s0[4], s1[4];
#pragma unroll
            for (int jj = 0; jj < 4; jj++) {
                const int f = 4 * g + jj;
                ulonglong2 wa = W2[f * 128 + lane];
                ulonglong2 wb = W2[f * 128 + lane + 32];
                ulonglong2 wc = W2[f * 128 + lane + 64];
                ulonglong2 wd = W2[f * 128 + lane + 96];
                u64 a0 = 0ull, a1 = 0ull;
                FMA2(a0, F0[0], wa.x, a0);  FMA2(a1, F1[0], wa.x, a1);
                FMA2(a0, F0[1], wa.y, a0);  FMA2(a1, F1[1], wa.y, a1);
                FMA2(a0, F0[2], wb.x, a0);  FMA2(a1, F1[2], wb.x, a1);
                FMA2(a0, F0[3], wb.y, a0);  FMA2(a1, F1[3], wb.y, a1);
                FMA2(a0, F0[4], wc.x, a0);  FMA2(a1, F1[4], wc.x, a1);
                FMA2(a0, F0[5], wc.y, a0);  FMA2(a1, F1[5], wc.y, a1);
                FMA2(a0, F0[6], wd.x, a0);  FMA2(a1, F1[6], wd.x, a1);
                FMA2(a0, F0[7], wd.y, a0);  FMA2(a1, F1[7], wd.y, a1);
                float2 p0 = *reinterpret_cast<float2*>(&a0);
                float2 p1 = *reinterpret_cast<float2*>(&a1);
                s0[jj] = p0.x + p0.y;
                s1[jj] = p1.x + p1.y;
            }
            fold_write(s0, v0, out + (size_t)w0 * NFINE + 4 * g, lane);
            fold_write(s1, v1, out + (size_t)w1 * NFINE + 4 * g, lane);
        }
    }
}

extern "C" void kernel_launch(void* const* d_in, const int* in_sizes, int n_in,
                              void* d_out, int out_size)
{
    const float* hidden = (const float*)d_in[0];
    const float* slot   = (const float*)d_in[1];
    const int*   labels = (const int*)d_in[2];
    const int*   pB     = (const int*)d_in[3];
    const int*   pI     = (const int*)d_in[4];
    float* out = (float*)d_out;

    cudaMemsetAsync(out, 0, (size_t)out_size * sizeof(float), 0);

    span_index_kernel<<<BATCH, 256>>>(labels, pB);

    span_project_kernel<<<148 * 3, 256>>>(hidden, slot, labels, pI, out);
}

// round 4
// speedup vs baseline: 2.4783x; 1.0010x over previous
#include <cuda_runtime.h>
#include <cstddef>
#include <cstdint>

#define BATCH 64
#define SEQ   2048
#define DIM   512
#define NFINE 16
#define MSPAN 512

typedef unsigned long long u64;

// Blackwell packed fp32x2 math (SASS FFMA2/FADD2) — PTX-only.
#define FMA2(d,a,b,c) asm("fma.rn.f32x2 %0, %1, %2, %3;" : "=l"(d) : "l"(a), "l"(b), "l"(c))
#define ADD2(d,a,b)   asm("add.rn.f32x2 %0, %1, %2;" : "=l"(d) : "l"(a), "l"(b))

__device__ int g_cnt;    // total valid spans
__device__ int g_fetch;  // dynamic work ticket
// compact span list: start token (global), end token (global), output span idx
__device__ int g_spanP[BATCH * MSPAN];
__device__ int g_spanE[BATCH * MSPAN];
__device__ int g_spanW[BATCH * MSPAN];

__global__ void init_counters() { g_cnt = 0; g_fetch = 0; }

// ---------------------------------------------------------------------------
// Kernel A: per batch row, compact B-tag positions via block scan, then emit
// (start, end, out_idx) triples into the global compact worklist.
// ---------------------------------------------------------------------------
__global__ void __launch_bounds__(256) span_index_kernel(
    const int* __restrict__ labels, const int* __restrict__ pB)
{
    __shared__ int Bpos[MSPAN + 1];
    __shared__ int s_base, s_n;

    const int b = blockIdx.x;
    const int t = threadIdx.x;
    const int cB = *pB;
    const int* row = labels + (size_t)b * SEQ;

    const int s0 = t * 8;
    int flags[8];
    int cnt = 0;
#pragma unroll
    for (int j = 0; j < 8; j++) {
        int lab = row[s0 + j];
        flags[j] = (lab == cB) ? 1 : 0;
        cnt += flags[j];
    }

    const int lane = t & 31;
    const int warp = t >> 5;
    int inc = cnt;
#pragma unroll
    for (int o = 1; o < 32; o <<= 1) {
        int v = __shfl_up_sync(0xffffffffu, inc, o);
        if (lane >= o) inc += v;
    }
    __shared__ int wsum[8];
    if (lane == 31) wsum[warp] = inc;
    __syncthreads();
    if (t < 8) {
        int v = wsum[t];
#pragma unroll
        for (int o = 1; o < 8; o <<= 1) {
            int u = __shfl_up_sync(0xffu, v, o);
            if (t >= o) v += u;
        }
        wsum[t] = v;
    }
    __syncthreads();
    int excl = inc - cnt + (warp > 0 ? wsum[warp - 1] : 0);

    int idx = excl;
#pragma unroll
    for (int j = 0; j < 8; j++) {
        if (flags[j]) {
            if (idx <= MSPAN) Bpos[idx] = s0 + j;
            idx++;
        }
    }
    if (t == 255) {
        int nB = excl + cnt;
        int n = nB < MSPAN ? nB : MSPAN;
        s_n = n;
        s_base = atomicAdd(&g_cnt, n);
    }
    __syncthreads();

    const int n = s_n;
    const int base = s_base;
    const int nBfull = (n < MSPAN) ? n : MSPAN;  // entries present in Bpos up to n(+1)
    for (int k = t; k < n; k += 256) {
        int p = Bpos[k];
        int pend = (k + 1 < nBfull || (k + 1 == MSPAN && idx > MSPAN)) ? Bpos[k + 1] : SEQ;
        // simpler & safe: if a (k+1)-th B exists anywhere, Bpos[k+1] was written
        // (we wrote idx <= MSPAN). Recompute cleanly:
        pend = SEQ;
        if (k + 1 < n) pend = Bpos[k + 1];
        else {
            // k == n-1: next B may exist beyond cap (k+1 == MSPAN slot written)
            // or beyond n-1 within cap when n == nB (no more B) -> SEQ.
            // Bpos[k+1] is valid iff total B count > k+1; detect via sentinel:
            // we conservatively use Bpos[k+1] only when it was written this pass.
            // Handled below via s_hasnext.
        }
        g_spanP[base + k] = b * SEQ + p;
        g_spanE[base + k] = b * SEQ + pend;
        g_spanW[base + k] = b * MSPAN + k;
    }
    // fix the last span's end if a (n)-th B tag exists (span cut by next B)
    __syncthreads();
    if (t == 255) {
        int nBtotal = excl + cnt;
        if (n > 0 && nBtotal > n) {   // there is a B tag at index n (== MSPAN cap or n<nB)
            g_spanE[base + n - 1] = b * SEQ + Bpos[n];  // Bpos[n] written (n <= MSPAN)
        }
    }
}

// ---------------------------------------------------------------------------
// Tree-fold 4 per-lane partials across the warp in 6 SHFLs; 4 lanes write.
// ---------------------------------------------------------------------------
__device__ __forceinline__ void fold_write(
    const float sc[4], bool valid, float* __restrict__ dst, int lane)
{
    float send0 = (lane & 16) ? sc[0] : sc[2];
    float r0 = __shfl_xor_sync(0xffffffffu, send0, 16);
    float n0 = ((lane & 16) ? sc[2] : sc[0]) + r0;
    float send1 = (lane & 16) ? sc[1] : sc[3];
    float r1 = __shfl_xor_sync(0xffffffffu, send1, 16);
    float n1 = ((lane & 16) ? sc[3] : sc[1]) + r1;

    float send = (lane & 8) ? n0 : n1;
    float r = __shfl_xor_sync(0xffffffffu, send, 8);
    float v = ((lane & 8) ? n1 : n0) + r;

    v += __shfl_xor_sync(0xffffffffu, v, 4);
    v += __shfl_xor_sync(0xffffffffu, v, 2);
    v += __shfl_xor_sync(0xffffffffu, v, 1);

    if (valid && (lane & 7) == 0) {
        int floc = (((lane >> 4) & 1) << 1) | ((lane >> 3) & 1);
        dst[floc] = v;
    }
}

// ---------------------------------------------------------------------------
// Kernel B: persistent warps, dynamic 2-span tickets, interleaved dual-span
// segment-sum (overlapped DRAM latency), shared-W projection, f32x2 math.
// ---------------------------------------------------------------------------
__global__ void __launch_bounds__(256, 3) span_project_kernel(
    const float* __restrict__ hidden,
    const float* __restrict__ slot,   // [DIM][NFINE]
    const int*   __restrict__ labels, // flat [BATCH*SEQ]
    const int*   __restrict__ pI,
    float* __restrict__ out)          // [BATCH][MSPAN][NFINE]
{
    __shared__ __align__(16) float Wsh[NFINE * DIM];  // Wsh[f*512 + d]
    for (int i = threadIdx.x; i < DIM * NFINE; i += blockDim.x) {
        int d = i >> 4;
        int f = i & 15;
        Wsh[f * DIM + d] = slot[i];
    }
    __syncthreads();
    const ulonglong2* W2 = reinterpret_cast<const ulonglong2*>(Wsh);

    const int cI = *pI;
    const int lane = threadIdx.x & 31;
    const int total = g_cnt;

    for (;;) {
        int i;
        if (lane == 0) i = atomicAdd(&g_fetch, 2);
        i = __shfl_sync(0xffffffffu, i, 0);
        if (i >= total) break;
        const bool v1 = (i + 1 < total);

        const int P0 = g_spanP[i];
        const int E0 = g_spanE[i];
        const int O0 = g_spanW[i];
        const int P1 = v1 ? g_spanP[i + 1] : P0;
        const int E1 = v1 ? g_spanE[i + 1] : P0;  // empty scan range when !v1
        const int O1 = v1 ? g_spanW[i + 1] : 0;

        // ---- head rows of both spans: 8 independent LDG.128 ----
        u64 F0[8], F1[8];
        {
            const ulonglong2* h0 =
                reinterpret_cast<const ulonglong2*>(hidden + (size_t)P0 * DIM);
            const ulonglong2* h1 =
                reinterpret_cast<const ulonglong2*>(hidden + (size_t)P1 * DIM);
            ulonglong2 a0 = __ldg(h0 + lane),      a1 = __ldg(h1 + lane);
            ulonglong2 b0 = __ldg(h0 + lane + 32), b1 = __ldg(h1 + lane + 32);
            ulonglong2 c0 = __ldg(h0 + lane + 64), c1 = __ldg(h1 + lane + 64);
            ulonglong2 d0 = __ldg(h0 + lane + 96), d1 = __ldg(h1 + lane + 96);
            F0[0] = a0.x; F0[1] = a0.y; F0[2] = b0.x; F0[3] = b0.y;
            F0[4] = c0.x; F0[5] = c0.y; F0[6] = d0.x; F0[7] = d0.y;
            F1[0] = a1.x; F1[1] = a1.y; F1[2] = b1.x; F1[3] = b1.y;
            F1[4] = c1.x; F1[5] = c1.y; F1[6] = d1.x; F1[7] = d1.y;
        }

        // ---- interleaved I-token accumulation for both spans ----
        int s0 = P0 + 1, s1 = P1 + 1;
        unsigned m0 = 0, m1 = 0;
        for (;;) {
            if (m0 == 0 && s0 < E0) {
                int ss = s0 + lane;
                bool hit = (ss < E0) && (__ldg(labels + ss) == cI);
                m0 = __ballot_sync(0xffffffffu, hit);
                s0 += 32;
            }
            if (m1 == 0 && s1 < E1) {
                int ss = s1 + lane;
                bool hit = (ss < E1) && (__ldg(labels + ss) == cI);
                m1 = __ballot_sync(0xffffffffu, hit);
                s1 += 32;
            }
            if ((m0 | m1) == 0) {
                if (s0 >= E0 && s1 >= E1) break;
                continue;
            }
            int t0 = -1, t1 = -1;
            if (m0) { int j = __ffs(m0) - 1; m0 &= m0 - 1; t0 = s0 - 32 + j; }
            if (m1) { int j = __ffs(m1) - 1; m1 &= m1 - 1; t1 = s1 - 32 + j; }

            ulonglong2 a0, b0, c0, d0, a1, b1, c1, d1;
            if (t0 >= 0) {
                const ulonglong2* h =
                    reinterpret_cast<const ulonglong2*>(hidden + (size_t)t0 * DIM);
                a0 = __ldg(h + lane);      b0 = __ldg(h + lane + 32);
                c0 = __ldg(h + lane + 64); d0 = __ldg(h + lane + 96);
            }
            if (t1 >= 0) {
                const ulonglong2* h =
                    reinterpret_cast<const ulonglong2*>(hidden + (size_t)t1 * DIM);
                a1 = __ldg(h + lane);      b1 = __ldg(h + lane + 32);
                c1 = __ldg(h + lane + 64); d1 = __ldg(h + lane + 96);
            }
            if (t0 >= 0) {
                ADD2(F0[0], F0[0], a0.x); ADD2(F0[1], F0[1], a0.y);
                ADD2(F0[2], F0[2], b0.x); ADD2(F0[3], F0[3], b0.y);
                ADD2(F0[4], F0[4], c0.x); ADD2(F0[5], F0[5], c0.y);
                ADD2(F0[6], F0[6], d0.x); ADD2(F0[7], F0[7], d0.y);
            }
            if (t1 >= 0) {
                ADD2(F1[0], F1[0], a1.x); ADD2(F1[1], F1[1], a1.y);
                ADD2(F1[2], F1[2], b1.x); ADD2(F1[3], F1[3], b1.y);
                ADD2(F1[4], F1[4], c1.x); ADD2(F1[5], F1[5], c1.y);
                ADD2(F1[6], F1[6], d1.x); ADD2(F1[7], F1[7], d1.y);
            }
        }

        // ---- projection: 4 groups of 4 filters; W LDS shared by both spans ----
#pragma unroll
        for (int g = 0; g < 4; g++) {
            float sc0[4], sc1[4];
#pragma unroll
            for (int jj = 0; jj < 4; jj++) {
                const int f = 4 * g + jj;
                ulonglong2 wa = W2[f * 128 + lane];
                ulonglong2 wb = W2[f * 128 + lane + 32];
                ulonglong2 wc = W2[f * 128 + lane + 64];
                ulonglong2 wd = W2[f * 128 + lane + 96];
                u64 a0 = 0ull, a1 = 0ull;
                FMA2(a0, F0[0], wa.x, a0);  FMA2(a1, F1[0], wa.x, a1);
                FMA2(a0, F0[1], wa.y, a0);  FMA2(a1, F1[1], wa.y, a1);
                FMA2(a0, F0[2], wb.x, a0);  FMA2(a1, F1[2], wb.x, a1);
                FMA2(a0, F0[3], wb.y, a0);  FMA2(a1, F1[3], wb.y, a1);
                FMA2(a0, F0[4], wc.x, a0);  FMA2(a1, F1[4], wc.x, a1);
                FMA2(a0, F0[5], wc.y, a0);  FMA2(a1, F1[5], wc.y, a1);
                FMA2(a0, F0[6], wd.x, a0);  FMA2(a1, F1[6], wd.x, a1);
                FMA2(a0, F0[7], wd.y, a0);  FMA2(a1, F1[7], wd.y, a1);
                float2 p0 = *reinterpret_cast<float2*>(&a0);
                float2 p1 = *reinterpret_cast<float2*>(&a1);
                sc0[jj] = p0.x + p0.y;
                sc1[jj] = p1.x + p1.y;
            }
            fold_write(sc0, true, out + (size_t)O0 * NFINE + 4 * g, lane);
            fold_write(sc1, v1,   out + (size_t)O1 * NFINE + 4 * g, lane);
        }
    }
}

extern "C" void kernel_launch(void* const* d_in, const int* in_sizes, int n_in,
                              void* d_out, int out_size)
{
    const float* hidden = (const float*)d_in[0];
    const float* slot   = (const float*)d_in[1];
    const int*   labels = (const int*)d_in[2];
    const int*   pB     = (const int*)d_in[3];
    const int*   pI     = (const int*)d_in[4];
    float* out = (float*)d_out;

    cudaMemsetAsync(out, 0, (size_t)out_size * sizeof(float), 0);
    init_counters<<<1, 1>>>();
    span_index_kernel<<<BATCH, 256>>>(labels, pB);
    span_project_kernel<<<148 * 3, 256>>>(hidden, slot, labels, pI, out);
}